// round 7
// baseline (speedup 1.0000x reference)
#include <cuda_runtime.h>

// EA-LSTM fused persistent kernel, round 6: identical design to round 5
// (infra failure last round, no kernel signal). 3-way k-split (768 thr),
// slim packed weights (float2 f,o + float g), unified x|h SMEM operands.
// B=1024, T=365, Dd=32, Ds=27, H=256, 3H=768, O=1.
// Grid: 128 CTAs x 768 threads, M=8 batch elems per CTA.
// Unified reduction axis K = 32 (x) + 256 (h) = 288; group g covers
// k in [96g, 96g+96) for all three gates of its column:
//   per k: LDG.64 (wf,wo) + LDG.32 (wg) + 2x broadcast LDS.128
//          + 12 fma.rn.f32x2  -> fma-pipe becomes the binding resource.
// Groups 1,2 publish partials via SMEM; group 0 combines + state update;
// group 1 stages x_{t+1}; group 2 does the scalar output dot.
// All accumulation bit-exact fp32 (packed f32x2).

#define B_      1024
#define T_      365
#define DD      32
#define DS      27
#define H_      256
#define G3      768
#define M_      8
#define KTOT    288            // 32 x-k + 256 h-k
#define KG      96             // k per group
#define THREADS 768
#define CTAS    (B_ / M_)      // 128
#define PSTRIDE 257            // padded u64 stride for partials

typedef unsigned long long u64;

// slim packed weights over the unified k axis (k<32 -> W_ih row, else W_hh)
__device__ float2 WfoP[KTOT][256];   // (wf, wo) per column
__device__ float  WgP [KTOT][256];   // wg per column

__device__ __forceinline__ u64 pack2(float lo, float hi) {
    u64 r; asm("mov.b64 %0, {%1, %2};" : "=l"(r) : "f"(lo), "f"(hi)); return r;
}
__device__ __forceinline__ void unpack2(u64 v, float& lo, float& hi) {
    asm("mov.b64 {%0, %1}, %2;" : "=f"(lo), "=f"(hi) : "l"(v));
}
__device__ __forceinline__ void fma2(u64& d, u64 a, u64 b) {
    asm("fma.rn.f32x2 %0, %1, %2, %0;" : "+l"(d) : "l"(a), "l"(b));
}
__device__ __forceinline__ void add2(u64& d, u64 a) {
    asm("add.rn.f32x2 %0, %0, %1;" : "+l"(d) : "l"(a));
}
__device__ __forceinline__ float sigmoidf_(float x) {
    return __fdividef(1.0f, 1.0f + __expf(-x));
}
__device__ __forceinline__ float tanhf_(float x) {
    float e = __expf(-2.0f * x);
    return __fdividef(1.0f - e, 1.0f + e);
}

__global__ void __launch_bounds__(256)
repack_kernel(const float* __restrict__ Wih, const float* __restrict__ Whh) {
    const int i   = blockIdx.x * blockDim.x + threadIdx.x;  // 0 .. 288*256-1
    const int k   = i >> 8;
    const int col = i & 255;
    const float* s = (k < DD) ? (Wih + k * G3) : (Whh + (k - DD) * G3);
    WfoP[k][col] = make_float2(s[col], s[256 + col]);
    WgP [k][col] = s[512 + col];
}

// dynamic SMEM layout:
//   float xh[KTOT*M_]           operand buffer: k<32 = x_t, k>=32 = h (stride 8)
//   u64   p1[12*PSTRIDE]        partials from group 1
//   u64   p2[12*PSTRIDE]        partials from group 2
#define XH_BYTES  (KTOT * M_ * 4)                  // 9216
#define P_BYTES   (12 * PSTRIDE * 8)               // 24672
#define SMEM_BYTES (XH_BYTES + 2 * P_BYTES)        // 58560

__global__ void __launch_bounds__(THREADS, 1)
ealstm_kernel(const float* __restrict__ xd,      // [B, T, DD]
              const float* __restrict__ xs,      // [B, DS]
              const float* __restrict__ Wsh,     // [DS, H]
              const float* __restrict__ bias,    // [3H]
              const float* __restrict__ bias_s,  // [H]
              const float* __restrict__ Wout,    // [H, 1]
              const float* __restrict__ bout,    // [1]
              float* __restrict__ out)           // [B, T, 1]
{
    extern __shared__ __align__(16) char smem_raw[];
    float* xh = (float*)smem_raw;
    u64*   p1 = (u64*)(smem_raw + XH_BYTES);
    u64*   p2 = p1 + 12 * PSTRIDE;

    const int tid  = threadIdx.x;
    const int grp  = tid >> 8;              // 0, 1, 2
    const int col  = tid & 255;
    const int b0   = blockIdx.x * M_;
    const int lane = tid & 31;
    const int warp = tid >> 5;
    const int k0   = grp * KG;              // this group's k range start

    // zero h region of xh (indices [DD*M_, KTOT*M_))
    for (int i = DD * M_ + tid; i < KTOT * M_; i += THREADS) xh[i] = 0.0f;

    // group 1 stages x_t for t = 0 into the x region
    if (grp == 1) {
        const int m = col >> 5, k = col & 31;
        xh[k * M_ + m] = xd[((size_t)(b0 + m) * T_ + 0) * DD + k];
    }

    // group 0: biases, cell state, entity-aware input gate
    float bf = 0.0f, bo = 0.0f, bg = 0.0f;
    float c[M_], ig[M_];
    if (grp == 0) {
        bf = bias[col]; bo = bias[H_ + col]; bg = bias[2 * H_ + col];
        float s[M_];
        #pragma unroll
        for (int m = 0; m < M_; m++) { s[m] = bias_s[col]; c[m] = 0.0f; }
        #pragma unroll 1
        for (int k = 0; k < DS; k++) {
            const float w = Wsh[k * H_ + col];
            #pragma unroll
            for (int m = 0; m < M_; m++)
                s[m] = fmaf(xs[(b0 + m) * DS + k], w, s[m]);
        }
        #pragma unroll
        for (int m = 0; m < M_; m++) ig[m] = sigmoidf_(s[m]);
    }

    // group 2: output weights for the warp-level out-dot
    float wout[8];
    float b_out0 = 0.0f;
    if (grp == 2) {
        #pragma unroll
        for (int q = 0; q < 8; q++) wout[q] = Wout[lane + 32 * q];
        b_out0 = bout[0];
    }

    __syncthreads();

    for (int t = 0; t < T_; t++) {
        // ---- phase A: partial gate sums over this group's k range ----
        u64 aF[4], aO[4], aG[4];
        if (grp == 0) {
            const u64 bf2 = pack2(bf, bf), bo2 = pack2(bo, bo), bg2 = pack2(bg, bg);
            #pragma unroll
            for (int p = 0; p < 4; p++) { aF[p] = bf2; aO[p] = bo2; aG[p] = bg2; }
        } else {
            #pragma unroll
            for (int p = 0; p < 4; p++) { aF[p] = 0ull; aO[p] = 0ull; aG[p] = 0ull; }
        }

        {
            const float2* wfo_p = &WfoP[k0][col];
            const float*  wg_p  = &WgP[k0][col];
            const float*  hb    = xh + k0 * M_;
            #pragma unroll 2
            for (int k = 0; k < KG; k++) {
                const float2 wfo = __ldcg(wfo_p + k * 256);
                const float  wg  = __ldcg(wg_p  + k * 256);
                const u64 wf2 = pack2(wfo.x, wfo.x);
                const u64 wo2 = pack2(wfo.y, wfo.y);
                const u64 wg2 = pack2(wg, wg);
                const ulonglong2 hA = *(const ulonglong2*)(hb + k * M_);
                const ulonglong2 hB = *(const ulonglong2*)(hb + k * M_ + 4);
                fma2(aF[0], wf2, hA.x); fma2(aF[1], wf2, hA.y);
                fma2(aF[2], wf2, hB.x); fma2(aF[3], wf2, hB.y);
                fma2(aO[0], wo2, hA.x); fma2(aO[1], wo2, hA.y);
                fma2(aO[2], wo2, hB.x); fma2(aO[3], wo2, hB.y);
                fma2(aG[0], wg2, hA.x); fma2(aG[1], wg2, hA.y);
                fma2(aG[2], wg2, hB.x); fma2(aG[3], wg2, hB.y);
            }
        }

        // groups 1, 2 publish partials ([p][col] layout, conflict-free)
        if (grp == 1) {
            #pragma unroll
            for (int p = 0; p < 4; p++) {
                p1[p * PSTRIDE + col]       = aF[p];
                p1[(4 + p) * PSTRIDE + col] = aO[p];
                p1[(8 + p) * PSTRIDE + col] = aG[p];
            }
        } else if (grp == 2) {
            #pragma unroll
            for (int p = 0; p < 4; p++) {
                p2[p * PSTRIDE + col]       = aF[p];
                p2[(4 + p) * PSTRIDE + col] = aO[p];
                p2[(8 + p) * PSTRIDE + col] = aG[p];
            }
        }

        __syncthreads();   // partials published; xh reads of step t done

        if (grp == 0) {
            // combine partials + state update
            #pragma unroll
            for (int p = 0; p < 4; p++) {
                add2(aF[p], p1[p * PSTRIDE + col]);
                add2(aO[p], p1[(4 + p) * PSTRIDE + col]);
                add2(aG[p], p1[(8 + p) * PSTRIDE + col]);
                add2(aF[p], p2[p * PSTRIDE + col]);
                add2(aO[p], p2[(4 + p) * PSTRIDE + col]);
                add2(aG[p], p2[(8 + p) * PSTRIDE + col]);
            }
            float hn[M_];
            #pragma unroll
            for (int p = 0; p < 4; p++) {
                float f0, f1, o0, o1, g0, g1;
                unpack2(aF[p], f0, f1);
                unpack2(aO[p], o0, o1);
                unpack2(aG[p], g0, g1);
                const int m0 = 2 * p, m1 = 2 * p + 1;
                c[m0] = sigmoidf_(f0) * c[m0] + ig[m0] * tanhf_(g0);
                c[m1] = sigmoidf_(f1) * c[m1] + ig[m1] * tanhf_(g1);
                hn[m0] = sigmoidf_(o0) * tanhf_(c[m0]);
                hn[m1] = sigmoidf_(o1) * tanhf_(c[m1]);
            }
            // publish h into xh (h region, stride-8 aligned, vectorized)
            float* hd = xh + (DD + col) * M_;
            *(float4*)(hd)     = make_float4(hn[0], hn[1], hn[2], hn[3]);
            *(float4*)(hd + 4) = make_float4(hn[4], hn[5], hn[6], hn[7]);
        } else if (grp == 1) {
            // stage x for t+1 into the x region (disjoint from h region)
            if (t + 1 < T_) {
                const int m = col >> 5, k = col & 31;
                xh[k * M_ + m] = xd[((size_t)(b0 + m) * T_ + (t + 1)) * DD + k];
            }
        }

        __syncthreads();   // xh (h_t and x_{t+1}) published

        // ---- output dot (group 2 warps 16..23, batch elem w = warp-16) ----
        // reads xh h-region (read-only during next phase A) -> race-free
        if (grp == 2) {
            const int w = warp - 16;
            float a = 0.0f;
            #pragma unroll
            for (int q = 0; q < 8; q++)
                a = fmaf(xh[(DD + lane + 32 * q) * M_ + w], wout[q], a);
            #pragma unroll
            for (int off = 16; off > 0; off >>= 1)
                a += __shfl_down_sync(0xffffffffu, a, off);
            if (lane == 0)
                out[(size_t)(b0 + w) * T_ + t] = a + b_out0;
        }
    }
}

extern "C" void kernel_launch(void* const* d_in, const int* in_sizes, int n_in,
                              void* d_out, int out_size) {
    const float* xd     = (const float*)d_in[0];  // x_dynamic [1024,365,32]
    const float* xs     = (const float*)d_in[1];  // x_static  [1024,27]
    const float* Wih    = (const float*)d_in[2];  // [32,768]
    const float* Whh    = (const float*)d_in[3];  // [256,768]
    const float* Wsh    = (const float*)d_in[4];  // [27,256]
    const float* bias   = (const float*)d_in[5];  // [768]
    const float* bias_s = (const float*)d_in[6];  // [256]
    const float* Wout   = (const float*)d_in[7];  // [256,1]
    const float* bout   = (const float*)d_in[8];  // [1]
    float* out = (float*)d_out;                   // [1024,365,1]

    // one-time-effect, idempotent attribute set; clear any benign error so it
    // can't leak into the harness's error checks.
    (void)cudaFuncSetAttribute(ealstm_kernel,
                               cudaFuncAttributeMaxDynamicSharedMemorySize,
                               SMEM_BYTES);
    (void)cudaGetLastError();

    repack_kernel<<<KTOT, 256>>>(Wih, Whh);
    ealstm_kernel<<<CTAS, THREADS, SMEM_BYTES>>>(xd, xs, Wsh, bias, bias_s,
                                                 Wout, bout, out);
}